// round 1
// baseline (speedup 1.0000x reference)
#include <cuda_runtime.h>
#include <cuda_bf16.h>
#include <stdint.h>

// Problem constants (fixed by the dataset)
#define N_NODES   10000
#define N_EDGES   160000
#define F_IN      512     // per-half feature width (h and h_N each 512)
#define K_TOT     1024    // concat width
#define H_FEATS   512
#define N_CLASSES 128

// ---------------------------------------------------------------------------
// Device scratch (no allocations allowed -> static __device__ globals)
// ---------------------------------------------------------------------------
__device__ int   g_cnt[N_NODES];
__device__ int   g_cur[N_NODES];
__device__ int   g_off[N_NODES + 1];
__device__ int   g_adj[N_EDGES];
__device__ float g_hN [(size_t)N_NODES * F_IN];
__device__ float g_h1 [(size_t)N_NODES * H_FEATS];
__device__ float g_h1N[(size_t)N_NODES * H_FEATS];

// ---------------------------------------------------------------------------
// CSR build
// ---------------------------------------------------------------------------
__global__ void zero_counts_kernel() {
    int i = blockIdx.x * blockDim.x + threadIdx.x;
    if (i < N_NODES) { g_cnt[i] = 0; g_cur[i] = 0; }
}

__global__ void count_kernel(const int* __restrict__ dst) {
    int e = blockIdx.x * blockDim.x + threadIdx.x;
    if (e < N_EDGES) atomicAdd(&g_cnt[dst[e]], 1);
}

// Single-block exclusive scan over g_cnt -> g_off
__global__ void scan_kernel() {
    __shared__ int sh[1024];
    int running = 0;
    for (int base = 0; base < N_NODES; base += 1024) {
        int i = base + threadIdx.x;
        int v = (i < N_NODES) ? g_cnt[i] : 0;
        sh[threadIdx.x] = v;
        __syncthreads();
        #pragma unroll
        for (int off = 1; off < 1024; off <<= 1) {
            int t = 0;
            if ((int)threadIdx.x >= off) t = sh[threadIdx.x - off];
            __syncthreads();
            sh[threadIdx.x] += t;
            __syncthreads();
        }
        if (i < N_NODES) g_off[i] = running + sh[threadIdx.x] - v;  // exclusive
        int total = sh[1023];
        __syncthreads();            // everyone done reading sh before next chunk
        running += total;
    }
    if (threadIdx.x == 0) g_off[N_NODES] = running;
}

__global__ void fill_kernel(const int* __restrict__ src, const int* __restrict__ dst) {
    int e = blockIdx.x * blockDim.x + threadIdx.x;
    if (e < N_EDGES) {
        int d = dst[e];
        int p = atomicAdd(&g_cur[d], 1);
        g_adj[g_off[d] + p] = src[e];
    }
}

// ---------------------------------------------------------------------------
// Segment-mean aggregation: one block per destination node, 128 thr x float4
// feats fixed at 512 for both layers.
// ---------------------------------------------------------------------------
__global__ void agg_kernel(const float* __restrict__ H, float* __restrict__ out) {
    int n   = blockIdx.x;
    int deg = g_cnt[n];
    int st  = g_off[n];
    int c4  = threadIdx.x;   // float4 index 0..127 (128*4 = 512 feats)

    float4 acc = make_float4(0.f, 0.f, 0.f, 0.f);
    int e = 0;
    // unroll-by-2 with adj prefetch to expose a little MLP
    for (; e + 1 < deg; e += 2) {
        int s0 = g_adj[st + e];
        int s1 = g_adj[st + e + 1];
        float4 v0 = *(const float4*)(H + (size_t)s0 * F_IN + c4 * 4);
        float4 v1 = *(const float4*)(H + (size_t)s1 * F_IN + c4 * 4);
        acc.x += v0.x + v1.x; acc.y += v0.y + v1.y;
        acc.z += v0.z + v1.z; acc.w += v0.w + v1.w;
    }
    if (e < deg) {
        int s0 = g_adj[st + e];
        float4 v0 = *(const float4*)(H + (size_t)s0 * F_IN + c4 * 4);
        acc.x += v0.x; acc.y += v0.y; acc.z += v0.z; acc.w += v0.w;
    }
    float inv = (deg > 0) ? (1.0f / (float)deg) : 0.0f;
    acc.x *= inv; acc.y *= inv; acc.z *= inv; acc.w *= inv;
    *(float4*)(out + (size_t)n * F_IN + c4 * 4) = acc;
}

// ---------------------------------------------------------------------------
// SGEMM: C[M,N] = concat(A0,A1)[M,1024] @ B[1024,N] + bias (+ReLU)
// A0/A1 row-major with row stride 512 (virtual K-concat).
// 128x128 block tile, BK=8, 256 threads, 8x8 register microtile.
// ---------------------------------------------------------------------------
__global__ __launch_bounds__(256, 2)
void sgemm_kernel(const float* __restrict__ A0, const float* __restrict__ A1,
                  const float* __restrict__ B,  const float* __restrict__ bias,
                  float* __restrict__ C, int M, int N, int do_relu) {
    __shared__ float As[8][128];
    __shared__ float Bs[8][128];

    const int t        = threadIdx.x;
    const int blockRow = blockIdx.y * 128;
    const int blockCol = blockIdx.x * 128;
    const int tRow     = (t / 16) * 8;
    const int tCol     = (t % 16) * 8;

    // A-tile loader mapping: 128 rows x 8 cols = 1024 floats / 256 thr = 4 each
    const int aRow  = t >> 1;        // 0..127
    const int aCol4 = (t & 1) * 4;   // 0 or 4
    // B-tile loader mapping: 8 rows x 128 cols
    const int bRow  = t >> 5;        // 0..7
    const int bCol4 = (t & 31) * 4;  // 0,4,...,124

    float acc[8][8];
    #pragma unroll
    for (int i = 0; i < 8; i++)
        #pragma unroll
        for (int j = 0; j < 8; j++) acc[i][j] = 0.f;

    const int gRowA = blockRow + aRow;
    const bool aValid = (gRowA < M);

    for (int k0 = 0; k0 < K_TOT; k0 += 8) {
        const float* Abase = (k0 < F_IN) ? (A0 + k0) : (A1 + (k0 - F_IN));
        float4 av = make_float4(0.f, 0.f, 0.f, 0.f);
        if (aValid) av = *(const float4*)(Abase + (size_t)gRowA * F_IN + aCol4);
        As[aCol4 + 0][aRow] = av.x;
        As[aCol4 + 1][aRow] = av.y;
        As[aCol4 + 2][aRow] = av.z;
        As[aCol4 + 3][aRow] = av.w;

        float4 bv = *(const float4*)(B + (size_t)(k0 + bRow) * N + blockCol + bCol4);
        *(float4*)(&Bs[bRow][bCol4]) = bv;

        __syncthreads();

        #pragma unroll
        for (int k = 0; k < 8; k++) {
            float ar[8], br[8];
            *(float4*)(&ar[0]) = *(const float4*)(&As[k][tRow]);
            *(float4*)(&ar[4]) = *(const float4*)(&As[k][tRow + 4]);
            *(float4*)(&br[0]) = *(const float4*)(&Bs[k][tCol]);
            *(float4*)(&br[4]) = *(const float4*)(&Bs[k][tCol + 4]);
            #pragma unroll
            for (int i = 0; i < 8; i++)
                #pragma unroll
                for (int j = 0; j < 8; j++)
                    acc[i][j] += ar[i] * br[j];
        }
        __syncthreads();
    }

    // epilogue: bias (+relu), guarded float4 stores
    float bvals[8];
    #pragma unroll
    for (int j = 0; j < 8; j++) bvals[j] = bias[blockCol + tCol + j];

    #pragma unroll
    for (int i = 0; i < 8; i++) {
        int gR = blockRow + tRow + i;
        if (gR < M) {
            #pragma unroll
            for (int j4 = 0; j4 < 8; j4 += 4) {
                float4 o;
                o.x = acc[i][j4 + 0] + bvals[j4 + 0];
                o.y = acc[i][j4 + 1] + bvals[j4 + 1];
                o.z = acc[i][j4 + 2] + bvals[j4 + 2];
                o.w = acc[i][j4 + 3] + bvals[j4 + 3];
                if (do_relu) {
                    o.x = fmaxf(o.x, 0.f); o.y = fmaxf(o.y, 0.f);
                    o.z = fmaxf(o.z, 0.f); o.w = fmaxf(o.w, 0.f);
                }
                *(float4*)(C + (size_t)gR * N + blockCol + tCol + j4) = o;
            }
        }
    }
}

// ---------------------------------------------------------------------------
// Launch
// Inputs (metadata order): h, W1, b1, W2, b2, src, dst
// ---------------------------------------------------------------------------
extern "C" void kernel_launch(void* const* d_in, const int* in_sizes, int n_in,
                              void* d_out, int out_size) {
    const float* h   = (const float*)d_in[0];
    const float* W1  = (const float*)d_in[1];
    const float* b1  = (const float*)d_in[2];
    const float* W2  = (const float*)d_in[3];
    const float* b2  = (const float*)d_in[4];
    const int*   src = (const int*)d_in[5];
    const int*   dst = (const int*)d_in[6];
    float*       out = (float*)d_out;

    float* hN  = nullptr; cudaGetSymbolAddress((void**)&hN,  g_hN);
    float* h1  = nullptr; cudaGetSymbolAddress((void**)&h1,  g_h1);
    float* h1N = nullptr; cudaGetSymbolAddress((void**)&h1N, g_h1N);

    const int TB = 256;

    // CSR build (fixed per call since src/dst fixed, but recomputed — cheap)
    zero_counts_kernel<<<(N_NODES + TB - 1) / TB, TB>>>();
    count_kernel<<<(N_EDGES + TB - 1) / TB, TB>>>(dst);
    scan_kernel<<<1, 1024>>>();
    fill_kernel<<<(N_EDGES + TB - 1) / TB, TB>>>(src, dst);

    // Layer 1
    agg_kernel<<<N_NODES, 128>>>(h, hN);
    {
        dim3 grid(H_FEATS / 128, (N_NODES + 127) / 128);
        sgemm_kernel<<<grid, 256>>>(h, hN, W1, b1, h1, N_NODES, H_FEATS, 1);
    }

    // Layer 2
    agg_kernel<<<N_NODES, 128>>>(h1, h1N);
    {
        dim3 grid(N_CLASSES / 128, (N_NODES + 127) / 128);
        sgemm_kernel<<<grid, 256>>>(h1, h1N, W2, b2, out, N_NODES, N_CLASSES, 0);
    }
}

// round 4
// speedup vs baseline: 1.7158x; 1.7158x over previous
#include <cuda_runtime.h>
#include <cuda_bf16.h>
#include <stdint.h>

// Problem constants (fixed by the dataset)
#define N_NODES   10000
#define N_EDGES   160000
#define F_IN      512
#define K_TOT     1024
#define H_FEATS   512
#define N_CLASSES 128

// ---------------------------------------------------------------------------
// Device scratch (no allocations allowed -> static __device__ globals)
// ---------------------------------------------------------------------------
__device__ int   g_cnt[N_NODES];
__device__ int   g_cur[N_NODES];
__device__ int   g_off[N_NODES + 1];
__device__ int   g_adj[N_EDGES];
__device__ float g_hN [(size_t)N_NODES * F_IN];
__device__ float g_h1 [(size_t)N_NODES * H_FEATS];
__device__ float g_h1N[(size_t)N_NODES * H_FEATS];
__device__ float g_W1t[(size_t)H_FEATS   * K_TOT];   // [512,1024]  = W1^T
__device__ float g_W2t[(size_t)N_CLASSES * K_TOT];   // [128,1024]  = W2^T

// ---------------------------------------------------------------------------
// CSR build
// ---------------------------------------------------------------------------
__global__ void zero_counts_kernel() {
    int i = blockIdx.x * blockDim.x + threadIdx.x;
    if (i < N_NODES) { g_cnt[i] = 0; g_cur[i] = 0; }
}
__global__ void count_kernel(const int* __restrict__ dst) {
    int e = blockIdx.x * blockDim.x + threadIdx.x;
    if (e < N_EDGES) atomicAdd(&g_cnt[dst[e]], 1);
}
__global__ void scan_kernel() {
    __shared__ int sh[1024];
    int running = 0;
    for (int base = 0; base < N_NODES; base += 1024) {
        int i = base + threadIdx.x;
        int v = (i < N_NODES) ? g_cnt[i] : 0;
        sh[threadIdx.x] = v;
        __syncthreads();
        #pragma unroll
        for (int off = 1; off < 1024; off <<= 1) {
            int t = 0;
            if ((int)threadIdx.x >= off) t = sh[threadIdx.x - off];
            __syncthreads();
            sh[threadIdx.x] += t;
            __syncthreads();
        }
        if (i < N_NODES) g_off[i] = running + sh[threadIdx.x] - v;
        int total = sh[1023];
        __syncthreads();
        running += total;
    }
    if (threadIdx.x == 0) g_off[N_NODES] = running;
}
__global__ void fill_kernel(const int* __restrict__ src, const int* __restrict__ dst) {
    int e = blockIdx.x * blockDim.x + threadIdx.x;
    if (e < N_EDGES) {
        int d = dst[e];
        int p = atomicAdd(&g_cur[d], 1);
        g_adj[g_off[d] + p] = src[e];
    }
}

// ---------------------------------------------------------------------------
// Segment-mean aggregation: one block per destination node
// ---------------------------------------------------------------------------
__global__ void agg_kernel(const float* __restrict__ H, float* __restrict__ out) {
    int n   = blockIdx.x;
    int deg = g_cnt[n];
    int st  = g_off[n];
    int c4  = threadIdx.x;

    float4 acc = make_float4(0.f, 0.f, 0.f, 0.f);
    int e = 0;
    for (; e + 1 < deg; e += 2) {
        int s0 = g_adj[st + e];
        int s1 = g_adj[st + e + 1];
        float4 v0 = *(const float4*)(H + (size_t)s0 * F_IN + c4 * 4);
        float4 v1 = *(const float4*)(H + (size_t)s1 * F_IN + c4 * 4);
        acc.x += v0.x + v1.x; acc.y += v0.y + v1.y;
        acc.z += v0.z + v1.z; acc.w += v0.w + v1.w;
    }
    if (e < deg) {
        int s0 = g_adj[st + e];
        float4 v0 = *(const float4*)(H + (size_t)s0 * F_IN + c4 * 4);
        acc.x += v0.x; acc.y += v0.y; acc.z += v0.z; acc.w += v0.w;
    }
    float inv = (deg > 0) ? (1.0f / (float)deg) : 0.0f;
    acc.x *= inv; acc.y *= inv; acc.z *= inv; acc.w *= inv;
    *(float4*)(out + (size_t)n * F_IN + c4 * 4) = acc;
}

// ---------------------------------------------------------------------------
// Transpose: out[C,R] = in[R,C]^T
// ---------------------------------------------------------------------------
__global__ void transpose_kernel(const float* __restrict__ in, float* __restrict__ out,
                                 int R, int C) {
    __shared__ float tile[32][33];
    int c = blockIdx.x * 32 + threadIdx.x;
    int r = blockIdx.y * 32 + threadIdx.y;
    #pragma unroll
    for (int j = 0; j < 32; j += 8)
        if (r + j < R && c < C) tile[threadIdx.y + j][threadIdx.x] = in[(size_t)(r + j) * C + c];
    __syncthreads();
    int c2 = blockIdx.y * 32 + threadIdx.x;
    int r2 = blockIdx.x * 32 + threadIdx.y;
    #pragma unroll
    for (int j = 0; j < 32; j += 8)
        if (r2 + j < C && c2 < R) out[(size_t)(r2 + j) * R + c2] = tile[threadIdx.x][threadIdx.y + j];
}

// ---------------------------------------------------------------------------
// 3xTF32 mma.sync GEMM (fp32-accurate via hi/lo error compensation):
//   C[M,N] = concat(A0,A1)[M,1024] @ Wt[N,1024]^T + bias (+ReLU)
// block tile 128x128, BK=16, 2-stage cp.async double buffer.
// 8 warps (4 warpM x 2 warpN), warp tile 32x64 = 2x8 m16n8k8 tf32 tiles.
// Each operand x = hi + lo (hi = rna-tf32(x)); acc += hi*hi + hi*lo + lo*hi.
// ---------------------------------------------------------------------------
#define NSTAGES_K 64        // 1024 / 16

__device__ __forceinline__ void cp_async16(uint32_t dst, const void* src, int src_bytes) {
    asm volatile("cp.async.cg.shared.global [%0], [%1], 16, %2;"
                 :: "r"(dst), "l"(src), "r"(src_bytes));
}
__device__ __forceinline__ void cp_commit() {
    asm volatile("cp.async.commit_group;" ::: "memory");
}
template <int N>
__device__ __forceinline__ void cp_wait() {
    asm volatile("cp.async.wait_group %0;" :: "n"(N) : "memory");
}
__device__ __forceinline__ void mma_tf32(float* c, const uint32_t* a, const uint32_t* b) {
    asm volatile(
        "mma.sync.aligned.m16n8k8.row.col.f32.tf32.tf32.f32 "
        "{%0,%1,%2,%3}, {%4,%5,%6,%7}, {%8,%9}, {%0,%1,%2,%3};"
        : "+f"(c[0]), "+f"(c[1]), "+f"(c[2]), "+f"(c[3])
        : "r"(a[0]), "r"(a[1]), "r"(a[2]), "r"(a[3]), "r"(b[0]), "r"(b[1]));
}
__device__ __forceinline__ uint32_t f32_to_tf32_rna(float x) {
    uint32_t r;
    asm("cvt.rna.tf32.f32 %0, %1;" : "=r"(r) : "f"(x));
    return r;
}
// split: hi = rna-tf32(x) (f32-format bits), lo = x - hi (fed raw, HW truncates)
__device__ __forceinline__ void tf32_split(float x, uint32_t& hi, uint32_t& lo) {
    hi = f32_to_tf32_rna(x);
    lo = __float_as_uint(x - __uint_as_float(hi));
}

__global__ __launch_bounds__(256, 1)
void gemm_mma_kernel(const float* __restrict__ A0, const float* __restrict__ A1,
                     const float* __restrict__ Wt, const float* __restrict__ bias,
                     float* __restrict__ C, int M, int N, int do_relu) {
    __shared__ float As[2][128][20];
    __shared__ float Bs[2][128][20];

    const int t     = threadIdx.x;
    const int lane  = t & 31;
    const int wid   = t >> 5;
    const int warpM = wid & 3;           // 0..3 -> 32-row slices
    const int warpN = wid >> 2;          // 0..1 -> 64-col slices
    const int gid   = lane >> 2;         // 0..7
    const int tig   = lane & 3;          // 0..3
    const int m0    = blockIdx.y * 128;
    const int n0    = blockIdx.x * 128;

    const int lrow = t >> 1;             // 0..127
    const int lofs = (t & 1) * 8;        // float offset 0 or 8
    const int aRow = m0 + lrow;
    const int aOK  = (aRow < M) ? 16 : 0;
    const int aRowC = (aRow < M) ? aRow : 0;
    const float* Brow = Wt + (size_t)(n0 + lrow) * K_TOT;

    float acc[2][8][4];
    #pragma unroll
    for (int mt = 0; mt < 2; mt++)
        #pragma unroll
        for (int nt = 0; nt < 8; nt++)
            #pragma unroll
            for (int q = 0; q < 4; q++) acc[mt][nt][q] = 0.f;

    uint32_t aSm[2], bSm[2];
    #pragma unroll
    for (int bfi = 0; bfi < 2; bfi++) {
        aSm[bfi] = (uint32_t)__cvta_generic_to_shared(&As[bfi][lrow][lofs]);
        bSm[bfi] = (uint32_t)__cvta_generic_to_shared(&Bs[bfi][lrow][lofs]);
    }

    auto load_stage = [&](int s, int bf) {
        const float* Asrc = (s < 32) ? A0 : A1;
        const int kcol = (s & 31) * 16;
        const float* ap = Asrc + (size_t)aRowC * 512 + kcol + lofs;
        cp_async16(aSm[bf],      ap,     aOK);
        cp_async16(aSm[bf] + 16, ap + 4, aOK);
        const float* bp = Brow + s * 16 + lofs;
        cp_async16(bSm[bf],      bp,     16);
        cp_async16(bSm[bf] + 16, bp + 4, 16);
    };

    load_stage(0, 0);
    cp_commit();

    for (int s = 0; s < NSTAGES_K; s++) {
        const int bf = s & 1;
        if (s + 1 < NSTAGES_K) { load_stage(s + 1, bf ^ 1); cp_commit(); }
        if (s + 1 < NSTAGES_K) cp_wait<1>(); else cp_wait<0>();
        __syncthreads();

        #pragma unroll
        for (int kk = 0; kk < 16; kk += 8) {
            uint32_t ah[2][4], al[2][4], bh[8][2], bl[8][2];
            #pragma unroll
            for (int mt = 0; mt < 2; mt++) {
                int r = warpM * 32 + mt * 16 + gid;
                tf32_split(As[bf][r][kk + tig],         ah[mt][0], al[mt][0]);
                tf32_split(As[bf][r + 8][kk + tig],     ah[mt][1], al[mt][1]);
                tf32_split(As[bf][r][kk + tig + 4],     ah[mt][2], al[mt][2]);
                tf32_split(As[bf][r + 8][kk + tig + 4], ah[mt][3], al[mt][3]);
            }
            #pragma unroll
            for (int nt = 0; nt < 8; nt++) {
                int n = warpN * 64 + nt * 8 + gid;
                tf32_split(Bs[bf][n][kk + tig],     bh[nt][0], bl[nt][0]);
                tf32_split(Bs[bf][n][kk + tig + 4], bh[nt][1], bl[nt][1]);
            }
            #pragma unroll
            for (int mt = 0; mt < 2; mt++)
                #pragma unroll
                for (int nt = 0; nt < 8; nt++) {
                    mma_tf32(acc[mt][nt], al[mt], bh[nt]);  // lo*hi
                    mma_tf32(acc[mt][nt], ah[mt], bl[nt]);  // hi*lo
                    mma_tf32(acc[mt][nt], ah[mt], bh[nt]);  // hi*hi
                }
        }
        __syncthreads();
    }

    // ---- epilogue: bias (+relu) ----
    #pragma unroll
    for (int nt = 0; nt < 8; nt++) {
        int cbase = n0 + warpN * 64 + nt * 8 + tig * 2;
        float b0 = __ldg(&bias[cbase]);
        float b1 = __ldg(&bias[cbase + 1]);
        #pragma unroll
        for (int mt = 0; mt < 2; mt++) {
            int r0 = m0 + warpM * 32 + mt * 16 + gid;
            int r1 = r0 + 8;
            float2 o0, o1;
            o0.x = acc[mt][nt][0] + b0; o0.y = acc[mt][nt][1] + b1;
            o1.x = acc[mt][nt][2] + b0; o1.y = acc[mt][nt][3] + b1;
            if (do_relu) {
                o0.x = fmaxf(o0.x, 0.f); o0.y = fmaxf(o0.y, 0.f);
                o1.x = fmaxf(o1.x, 0.f); o1.y = fmaxf(o1.y, 0.f);
            }
            if (r0 < M) *(float2*)(C + (size_t)r0 * N + cbase) = o0;
            if (r1 < M) *(float2*)(C + (size_t)r1 * N + cbase) = o1;
        }
    }
}

// ---------------------------------------------------------------------------
// Launch.  Inputs (metadata order): h, W1, b1, W2, b2, src, dst
// ---------------------------------------------------------------------------
extern "C" void kernel_launch(void* const* d_in, const int* in_sizes, int n_in,
                              void* d_out, int out_size) {
    const float* h   = (const float*)d_in[0];
    const float* W1  = (const float*)d_in[1];
    const float* b1  = (const float*)d_in[2];
    const float* W2  = (const float*)d_in[3];
    const float* b2  = (const float*)d_in[4];
    const int*   src = (const int*)d_in[5];
    const int*   dst = (const int*)d_in[6];
    float*       out = (float*)d_out;

    float* hN  = nullptr; cudaGetSymbolAddress((void**)&hN,  g_hN);
    float* h1  = nullptr; cudaGetSymbolAddress((void**)&h1,  g_h1);
    float* h1N = nullptr; cudaGetSymbolAddress((void**)&h1N, g_h1N);
    float* W1t = nullptr; cudaGetSymbolAddress((void**)&W1t, g_W1t);
    float* W2t = nullptr; cudaGetSymbolAddress((void**)&W2t, g_W2t);

    const int TB = 256;

    // CSR build
    zero_counts_kernel<<<(N_NODES + TB - 1) / TB, TB>>>();
    count_kernel<<<(N_EDGES + TB - 1) / TB, TB>>>(dst);
    scan_kernel<<<1, 1024>>>();
    fill_kernel<<<(N_EDGES + TB - 1) / TB, TB>>>(src, dst);

    // Weight transposes
    {
        dim3 blk(32, 8);
        dim3 g1((H_FEATS + 31) / 32, (K_TOT + 31) / 32);
        transpose_kernel<<<g1, blk>>>(W1, W1t, K_TOT, H_FEATS);
        dim3 g2((N_CLASSES + 31) / 32, (K_TOT + 31) / 32);
        transpose_kernel<<<g2, blk>>>(W2, W2t, K_TOT, N_CLASSES);
    }

    const int MT = (N_NODES + 127) / 128;  // 79

    // Layer 1
    agg_kernel<<<N_NODES, 128>>>(h, hN);
    {
        dim3 grid(H_FEATS / 128, MT);
        gemm_mma_kernel<<<grid, 256>>>(h, hN, W1t, b1, h1, N_NODES, H_FEATS, 1);
    }

    // Layer 2
    agg_kernel<<<N_NODES, 128>>>(h1, h1N);
    {
        dim3 grid(N_CLASSES / 128, MT);
        gemm_mma_kernel<<<grid, 256>>>(h1, h1N, W2t, b2, out, N_NODES, N_CLASSES, 0);
    }
}

// round 5
// speedup vs baseline: 1.8904x; 1.1017x over previous
#include <cuda_runtime.h>
#include <cuda_bf16.h>
#include <stdint.h>

// Problem constants (fixed by the dataset)
#define N_NODES   10000
#define N_EDGES   160000
#define F_IN      512
#define K_TOT     1024
#define H_FEATS   512
#define N_CLASSES 128

// ---------------------------------------------------------------------------
// Device scratch
// ---------------------------------------------------------------------------
__device__ int   g_cnt[N_NODES];
__device__ int   g_cur[N_NODES];
__device__ int   g_off[N_NODES + 1];
__device__ int   g_adj[N_EDGES];
__device__ float g_hN [(size_t)N_NODES * F_IN];      // agg(h)
__device__ float g_h1 [(size_t)N_NODES * H_FEATS];   // relu(layer1)
__device__ float g_Y2 [(size_t)N_NODES * N_CLASSES]; // h1 @ W2_bot
__device__ float g_T2 [(size_t)N_NODES * N_CLASSES]; // agg(Y2)

// ---------------------------------------------------------------------------
// CSR build
// ---------------------------------------------------------------------------
__global__ void zero_counts_kernel() {
    int i = blockIdx.x * blockDim.x + threadIdx.x;
    if (i < N_NODES) { g_cnt[i] = 0; g_cur[i] = 0; }
}
__global__ void count_kernel(const int* __restrict__ dst) {
    int e = blockIdx.x * blockDim.x + threadIdx.x;
    if (e < N_EDGES) atomicAdd(&g_cnt[dst[e]], 1);
}
// single-block shuffle scan (1024 threads, 10 chunks, 3 syncs/chunk)
__global__ void scan_kernel() {
    __shared__ int wsum[32];
    __shared__ int chunk_total;
    const int lane = threadIdx.x & 31;
    const int wid  = threadIdx.x >> 5;
    int running = 0;
    for (int base = 0; base < N_NODES; base += 1024) {
        int i = base + threadIdx.x;
        int v = (i < N_NODES) ? g_cnt[i] : 0;
        int s = v;
        #pragma unroll
        for (int o = 1; o < 32; o <<= 1) {
            int u = __shfl_up_sync(0xffffffffu, s, o);
            if (lane >= o) s += u;
        }
        if (lane == 31) wsum[wid] = s;
        __syncthreads();
        if (wid == 0) {
            int ws = wsum[lane];
            #pragma unroll
            for (int o = 1; o < 32; o <<= 1) {
                int u = __shfl_up_sync(0xffffffffu, ws, o);
                if (lane >= o) ws += u;
            }
            wsum[lane] = ws;
            if (lane == 31) chunk_total = ws;
        }
        __syncthreads();
        int wpref = (wid > 0) ? wsum[wid - 1] : 0;
        if (i < N_NODES) g_off[i] = running + wpref + s - v;  // exclusive
        running += chunk_total;
        __syncthreads();
    }
    if (threadIdx.x == 0) g_off[N_NODES] = running;
}
__global__ void fill_kernel(const int* __restrict__ src, const int* __restrict__ dst) {
    int e = blockIdx.x * blockDim.x + threadIdx.x;
    if (e < N_EDGES) {
        int d = dst[e];
        int p = atomicAdd(&g_cur[d], 1);
        g_adj[g_off[d] + p] = src[e];
    }
}

// ---------------------------------------------------------------------------
// Segment-mean aggregation, width 512: one block (128 thr) per node
// ---------------------------------------------------------------------------
__global__ void agg512_kernel(const float* __restrict__ H, float* __restrict__ out) {
    int n   = blockIdx.x;
    int deg = g_cnt[n];
    int st  = g_off[n];
    int c4  = threadIdx.x;

    float4 acc = make_float4(0.f, 0.f, 0.f, 0.f);
    int e = 0;
    for (; e + 1 < deg; e += 2) {
        int s0 = g_adj[st + e];
        int s1 = g_adj[st + e + 1];
        float4 v0 = *(const float4*)(H + (size_t)s0 * 512 + c4 * 4);
        float4 v1 = *(const float4*)(H + (size_t)s1 * 512 + c4 * 4);
        acc.x += v0.x + v1.x; acc.y += v0.y + v1.y;
        acc.z += v0.z + v1.z; acc.w += v0.w + v1.w;
    }
    if (e < deg) {
        int s0 = g_adj[st + e];
        float4 v0 = *(const float4*)(H + (size_t)s0 * 512 + c4 * 4);
        acc.x += v0.x; acc.y += v0.y; acc.z += v0.z; acc.w += v0.w;
    }
    float inv = (deg > 0) ? (1.0f / (float)deg) : 0.0f;
    acc.x *= inv; acc.y *= inv; acc.z *= inv; acc.w *= inv;
    *(float4*)(out + (size_t)n * 512 + c4 * 4) = acc;
}

// width 128: 4 nodes per 128-thread block, 32 lanes per node
__global__ void agg128_kernel(const float* __restrict__ Y, float* __restrict__ T) {
    int n = blockIdx.x * 4 + (threadIdx.x >> 5);
    int lane = threadIdx.x & 31;
    if (n >= N_NODES) return;
    int deg = g_cnt[n];
    int st  = g_off[n];
    float4 acc = make_float4(0.f, 0.f, 0.f, 0.f);
    int e = 0;
    for (; e + 1 < deg; e += 2) {
        int s0 = g_adj[st + e];
        int s1 = g_adj[st + e + 1];
        float4 v0 = *(const float4*)(Y + (size_t)s0 * 128 + lane * 4);
        float4 v1 = *(const float4*)(Y + (size_t)s1 * 128 + lane * 4);
        acc.x += v0.x + v1.x; acc.y += v0.y + v1.y;
        acc.z += v0.z + v1.z; acc.w += v0.w + v1.w;
    }
    if (e < deg) {
        int s0 = g_adj[st + e];
        float4 v0 = *(const float4*)(Y + (size_t)s0 * 128 + lane * 4);
        acc.x += v0.x; acc.y += v0.y; acc.z += v0.z; acc.w += v0.w;
    }
    float inv = (deg > 0) ? (1.0f / (float)deg) : 0.0f;
    acc.x *= inv; acc.y *= inv; acc.z *= inv; acc.w *= inv;
    *(float4*)(T + (size_t)n * 128 + lane * 4) = acc;
}

// ---------------------------------------------------------------------------
// 3xTF32 mma.sync GEMM, B loaded DIRECTLY from W (k-major tile, no transpose):
//   C[M,N] = concatK(A0,A1)[M, ns*16] @ W[koff : koff+ns*16, 0:ldW][:, n0:n0+128]
//            (+ bias) (+ Cadd) (+ ReLU)
// block tile 128x128, BK=16, 2-stage cp.async double buffer, occ 2.
// As [2][128][20] (row-major, padded); Bs [2][16][136] (k-major, padded).
// 8 warps (4 warpM x 2 warpN), warp tile 32x64 = 2x8 m16n8k8 tiles, 3 MMAs each.
// ---------------------------------------------------------------------------
__device__ __forceinline__ void cp_async16(uint32_t dst, const void* src, int src_bytes) {
    asm volatile("cp.async.cg.shared.global [%0], [%1], 16, %2;"
                 :: "r"(dst), "l"(src), "r"(src_bytes));
}
__device__ __forceinline__ void cp_commit() {
    asm volatile("cp.async.commit_group;" ::: "memory");
}
template <int N>
__device__ __forceinline__ void cp_wait() {
    asm volatile("cp.async.wait_group %0;" :: "n"(N) : "memory");
}
__device__ __forceinline__ void mma_tf32(float* c, const uint32_t* a, const uint32_t* b) {
    asm volatile(
        "mma.sync.aligned.m16n8k8.row.col.f32.tf32.tf32.f32 "
        "{%0,%1,%2,%3}, {%4,%5,%6,%7}, {%8,%9}, {%0,%1,%2,%3};"
        : "+f"(c[0]), "+f"(c[1]), "+f"(c[2]), "+f"(c[3])
        : "r"(a[0]), "r"(a[1]), "r"(a[2]), "r"(a[3]), "r"(b[0]), "r"(b[1]));
}
__device__ __forceinline__ uint32_t f32_to_tf32_rna(float x) {
    uint32_t r;
    asm("cvt.rna.tf32.f32 %0, %1;" : "=r"(r) : "f"(x));
    return r;
}
__device__ __forceinline__ void tf32_split(float x, uint32_t& hi, uint32_t& lo) {
    hi = f32_to_tf32_rna(x);
    lo = __float_as_uint(x - __uint_as_float(hi));
}

__global__ __launch_bounds__(256, 2)
void gemm_mma_kernel(const float* __restrict__ A0, const float* __restrict__ A1,
                     const float* __restrict__ W, int ldW, int koff,
                     const float* __restrict__ bias, const float* __restrict__ Cadd,
                     float* __restrict__ C, int M, int N, int do_relu, int nstages) {
    __shared__ float As[2][128][20];
    __shared__ float Bs[2][16][136];

    const int t     = threadIdx.x;
    const int lane  = t & 31;
    const int wid   = t >> 5;
    const int warpM = wid & 3;
    const int warpN = wid >> 2;
    const int gid   = lane >> 2;
    const int tig   = lane & 3;
    const int m0    = blockIdx.y * 128;
    const int n0    = blockIdx.x * 128;

    // A loader: 128 rows x 16 floats; thread -> (row, 8-float half)
    const int lrow = t >> 1;
    const int lofs = (t & 1) * 8;
    const int aRow = m0 + lrow;
    const int aOK  = (aRow < M) ? 16 : 0;
    const int aRowC = (aRow < M) ? aRow : 0;
    // B loader: 16 k-rows x 32 float4 chunks; thread -> (krow, 2 chunks)
    const int bKrow = t >> 4;        // 0..15
    const int bC0   = t & 15;        // chunks bC0 and bC0+16

    float acc[2][8][4];
    #pragma unroll
    for (int mt = 0; mt < 2; mt++)
        #pragma unroll
        for (int nt = 0; nt < 8; nt++)
            #pragma unroll
            for (int q = 0; q < 4; q++) acc[mt][nt][q] = 0.f;

    uint32_t aSm[2], bSm[2];
    #pragma unroll
    for (int bfi = 0; bfi < 2; bfi++) {
        aSm[bfi] = (uint32_t)__cvta_generic_to_shared(&As[bfi][lrow][lofs]);
        bSm[bfi] = (uint32_t)__cvta_generic_to_shared(&Bs[bfi][bKrow][bC0 * 4]);
    }

    auto load_stage = [&](int s, int bf) {
        const float* Asrc = (A1 && s >= 32) ? A1 : A0;
        const int kcol = (s & 31) * 16;
        const float* ap = Asrc + (size_t)aRowC * 512 + kcol + lofs;
        cp_async16(aSm[bf],      ap,     aOK);
        cp_async16(aSm[bf] + 16, ap + 4, aOK);
        const float* bp = W + (size_t)(koff + s * 16 + bKrow) * ldW + n0 + bC0 * 4;
        cp_async16(bSm[bf],            bp,      16);
        cp_async16(bSm[bf] + 16 * 16,  bp + 64, 16);   // +16 chunks = +64 floats
    };

    load_stage(0, 0);
    cp_commit();

    for (int s = 0; s < nstages; s++) {
        const int bf = s & 1;
        if (s + 1 < nstages) { load_stage(s + 1, bf ^ 1); cp_commit(); cp_wait<1>(); }
        else                 { cp_wait<0>(); }
        __syncthreads();

        #pragma unroll
        for (int kk = 0; kk < 16; kk += 8) {
            uint32_t ah[2][4], al[2][4];
            #pragma unroll
            for (int mt = 0; mt < 2; mt++) {
                int r = warpM * 32 + mt * 16 + gid;
                tf32_split(As[bf][r][kk + tig],         ah[mt][0], al[mt][0]);
                tf32_split(As[bf][r + 8][kk + tig],     ah[mt][1], al[mt][1]);
                tf32_split(As[bf][r][kk + tig + 4],     ah[mt][2], al[mt][2]);
                tf32_split(As[bf][r + 8][kk + tig + 4], ah[mt][3], al[mt][3]);
            }
            #pragma unroll
            for (int nt = 0; nt < 8; nt++) {
                int n = warpN * 64 + nt * 8 + gid;
                uint32_t bh[2], bl[2];
                tf32_split(Bs[bf][kk + tig][n],     bh[0], bl[0]);
                tf32_split(Bs[bf][kk + tig + 4][n], bh[1], bl[1]);
                #pragma unroll
                for (int mt = 0; mt < 2; mt++) {
                    mma_tf32(acc[mt][nt], al[mt], bh);  // lo*hi
                    mma_tf32(acc[mt][nt], ah[mt], bl);  // hi*lo
                    mma_tf32(acc[mt][nt], ah[mt], bh);  // hi*hi
                }
            }
        }
        __syncthreads();
    }

    // ---- epilogue: bias + Cadd (+relu) ----
    #pragma unroll
    for (int nt = 0; nt < 8; nt++) {
        int cbase = n0 + warpN * 64 + nt * 8 + tig * 2;
        float b0 = bias ? __ldg(&bias[cbase])     : 0.f;
        float b1 = bias ? __ldg(&bias[cbase + 1]) : 0.f;
        #pragma unroll
        for (int mt = 0; mt < 2; mt++) {
            int r0 = m0 + warpM * 32 + mt * 16 + gid;
            int r1 = r0 + 8;
            float2 o0, o1;
            o0.x = acc[mt][nt][0] + b0; o0.y = acc[mt][nt][1] + b1;
            o1.x = acc[mt][nt][2] + b0; o1.y = acc[mt][nt][3] + b1;
            if (Cadd) {
                if (r0 < M) {
                    float2 t0 = *(const float2*)(Cadd + (size_t)r0 * N + cbase);
                    o0.x += t0.x; o0.y += t0.y;
                }
                if (r1 < M) {
                    float2 t1 = *(const float2*)(Cadd + (size_t)r1 * N + cbase);
                    o1.x += t1.x; o1.y += t1.y;
                }
            }
            if (do_relu) {
                o0.x = fmaxf(o0.x, 0.f); o0.y = fmaxf(o0.y, 0.f);
                o1.x = fmaxf(o1.x, 0.f); o1.y = fmaxf(o1.y, 0.f);
            }
            if (r0 < M) *(float2*)(C + (size_t)r0 * N + cbase) = o0;
            if (r1 < M) *(float2*)(C + (size_t)r1 * N + cbase) = o1;
        }
    }
}

// ---------------------------------------------------------------------------
// Launch.  Inputs (metadata order): h, W1, b1, W2, b2, src, dst
// out = h1 @ W2[0:512] + agg(h1 @ W2[512:1024]) + b2   (linearity of mean-agg)
// ---------------------------------------------------------------------------
extern "C" void kernel_launch(void* const* d_in, const int* in_sizes, int n_in,
                              void* d_out, int out_size) {
    const float* h   = (const float*)d_in[0];
    const float* W1  = (const float*)d_in[1];
    const float* b1  = (const float*)d_in[2];
    const float* W2  = (const float*)d_in[3];
    const float* b2  = (const float*)d_in[4];
    const int*   src = (const int*)d_in[5];
    const int*   dst = (const int*)d_in[6];
    float*       out = (float*)d_out;

    float* hN = nullptr; cudaGetSymbolAddress((void**)&hN, g_hN);
    float* h1 = nullptr; cudaGetSymbolAddress((void**)&h1, g_h1);
    float* Y2 = nullptr; cudaGetSymbolAddress((void**)&Y2, g_Y2);
    float* T2 = nullptr; cudaGetSymbolAddress((void**)&T2, g_T2);

    const int TB = 256;

    // CSR build
    zero_counts_kernel<<<(N_NODES + TB - 1) / TB, TB>>>();
    count_kernel<<<(N_EDGES + TB - 1) / TB, TB>>>(dst);
    scan_kernel<<<1, 1024>>>();
    fill_kernel<<<(N_EDGES + TB - 1) / TB, TB>>>(src, dst);

    const int MT = (N_NODES + 127) / 128;  // 79

    // ---- Layer 1: h1 = relu([h, agg(h)] @ W1 + b1) ----
    agg512_kernel<<<N_NODES, 128>>>(h, hN);
    {
        dim3 grid(H_FEATS / 128, MT);
        gemm_mma_kernel<<<grid, 256>>>(h, hN, W1, H_FEATS, 0,
                                       b1, nullptr, h1, N_NODES, H_FEATS, 1, 64);
    }

    // ---- Layer 2 ----
    // Y2 = h1 @ W2[512:1024]  (no bias)
    {
        dim3 grid(N_CLASSES / 128, MT);
        gemm_mma_kernel<<<grid, 256>>>(h1, nullptr, W2, N_CLASSES, 512,
                                       nullptr, nullptr, Y2, N_NODES, N_CLASSES, 0, 32);
    }
    // T2 = agg(Y2)   (width 128)
    agg128_kernel<<<(N_NODES + 3) / 4, 128>>>(Y2, T2);
    // out = h1 @ W2[0:512] + b2 + T2
    {
        dim3 grid(N_CLASSES / 128, MT);
        gemm_mma_kernel<<<grid, 256>>>(h1, nullptr, W2, N_CLASSES, 0,
                                       b2, T2, out, N_NODES, N_CLASSES, 0, 32);
    }
}